// round 1
// baseline (speedup 1.0000x reference)
#include <cuda_runtime.h>
#include <cuda_bf16.h>
#include <math.h>

// Problem constants (fixed by the dataset)
#define BB   8
#define NN   16384
#define CC   640
#define HH   256
#define OO   128
#define MTOT (BB * NN)          // 131072
#define THRESH 0.4f

// -------- scratch (__device__ globals; no runtime allocation allowed) --------
__device__ float g_scores[MTOT];
__device__ int   g_pos[MTOT];    // slot within batch if selected, else -1
__device__ int   g_src[MTOT];    // src_of[b*NN + slot] = n (within batch)
__device__ int   g_counts[BB];

// =====================================================================
// Kernel 1: GEMM1 (X @ w1) fused with relu -> dot(w2) -> sigmoid score
// CTA tile: 64 rows x 256 cols (full H), KT=16, 256 threads, 8x8/thread
// =====================================================================
__global__ __launch_bounds__(256) void k1_score(
    const float* __restrict__ X, const float* __restrict__ w1,
    const float* __restrict__ b1, const float* __restrict__ w2,
    const float* __restrict__ b2)
{
    __shared__ float sA[16][65];    // [k][m], padded (65*4=260 => bank +4 per k-step)
    __shared__ float sB[16][256];   // [k][n]

    const int tid = threadIdx.x;
    const int tx = tid & 31;        // covers N: n = tx + j*32
    const int ty = tid >> 5;        // covers M: m = ty + i*8
    const int m0 = blockIdx.x * 64;

    float acc[8][8];
#pragma unroll
    for (int i = 0; i < 8; i++)
#pragma unroll
        for (int j = 0; j < 8; j++) acc[i][j] = 0.f;

    const int arow = tid >> 2;          // 0..63
    const int ac4  = (tid & 3) * 4;     // 0,4,8,12

    for (int kt = 0; kt < CC; kt += 16) {
        // A tile: 64 x 16, transposed into sA[k][m]
        float4 va = *(const float4*)(X + (size_t)(m0 + arow) * CC + kt + ac4);
        sA[ac4 + 0][arow] = va.x;
        sA[ac4 + 1][arow] = va.y;
        sA[ac4 + 2][arow] = va.z;
        sA[ac4 + 3][arow] = va.w;
        // B tile: 16 x 256 (w1 row-major [C,H] is already [k][n])
#pragma unroll
        for (int p = 0; p < 4; p++) {
            int idx = tid + p * 256;        // f4 index 0..1023
            int r   = idx >> 6;             // 64 f4 per row
            int c4  = (idx & 63) * 4;
            *(float4*)&sB[r][c4] = *(const float4*)(w1 + (size_t)(kt + r) * HH + c4);
        }
        __syncthreads();
#pragma unroll
        for (int k = 0; k < 16; k++) {
            float a[8], bv[8];
#pragma unroll
            for (int i = 0; i < 8; i++) a[i] = sA[k][ty + i * 8];
#pragma unroll
            for (int j = 0; j < 8; j++) bv[j] = sB[k][tx + j * 32];
#pragma unroll
            for (int i = 0; i < 8; i++)
#pragma unroll
                for (int j = 0; j < 8; j++)
                    acc[i][j] = fmaf(a[i], bv[j], acc[i][j]);
        }
        __syncthreads();
    }

    // Epilogue: relu(h + b1), dot with w2 across N via shfl, sigmoid
    float w2v[8], b1v[8];
#pragma unroll
    for (int j = 0; j < 8; j++) {
        int n = tx + j * 32;
        w2v[j] = w2[n];
        b1v[j] = b1[n];
    }
    const float b2v = b2[0];
#pragma unroll
    for (int i = 0; i < 8; i++) {
        float part = 0.f;
#pragma unroll
        for (int j = 0; j < 8; j++) {
            float h = acc[i][j] + b1v[j];
            h = fmaxf(h, 0.f);
            part = fmaf(h, w2v[j], part);
        }
#pragma unroll
        for (int o = 16; o > 0; o >>= 1)
            part += __shfl_xor_sync(0xFFFFFFFFu, part, o);
        if (tx == 0) {
            float logit = part + b2v;
            g_scores[m0 + ty + i * 8] = 1.f / (1.f + expf(-logit));
        }
    }
}

// =====================================================================
// Kernel 2: per-batch stream-compaction scan (1 CTA per batch)
// 256 threads x 64 contiguous elements each
// =====================================================================
__global__ __launch_bounds__(256) void k_scan()
{
    const int b    = blockIdx.x;
    const int base = b << 14;           // b * NN
    const int t    = threadIdx.x;
    const int chunk = t * 64;

    int c = 0;
    for (int e = 0; e < 64; e++)
        c += (g_scores[base + chunk + e] > THRESH) ? 1 : 0;

    // block exclusive scan of per-thread counts
    const int lane = t & 31, wid = t >> 5;
    int v = c;
#pragma unroll
    for (int o = 1; o < 32; o <<= 1) {
        int u = __shfl_up_sync(0xFFFFFFFFu, v, o);
        if (lane >= o) v += u;
    }
    __shared__ int wsum[8];
    if (lane == 31) wsum[wid] = v;
    __syncthreads();
    int woff = 0;
    for (int w = 0; w < wid; w++) woff += wsum[w];
    int p = woff + v - c;               // exclusive prefix for this thread

    for (int e = 0; e < 64; e++) {
        int n = chunk + e;
        bool sel = g_scores[base + n] > THRESH;
        if (sel) {
            g_pos[base + n] = p;
            g_src[base + p] = n;
            p++;
        } else {
            g_pos[base + n] = -1;
        }
    }
    if (t == 255) g_counts[b] = p;      // total selected in batch
}

// =====================================================================
// Kernel 3: GEMM2 (X @ wo), epilogue scales by score and scatters the
// row directly into its compacted output slot.
// CTA tile 64 x 128, KT=16, 256 threads, 8x4/thread
// =====================================================================
__global__ __launch_bounds__(256) void k2_feats(
    const float* __restrict__ X, const float* __restrict__ wo,
    const float* __restrict__ bo, float* __restrict__ kp_out)
{
    __shared__ float sA[16][65];
    __shared__ float sB[16][128];

    const int tid = threadIdx.x;
    const int tx = tid & 31;
    const int ty = tid >> 5;
    const int m0 = blockIdx.x * 64;

    float acc[8][4];
#pragma unroll
    for (int i = 0; i < 8; i++)
#pragma unroll
        for (int j = 0; j < 4; j++) acc[i][j] = 0.f;

    const int arow = tid >> 2;
    const int ac4  = (tid & 3) * 4;

    for (int kt = 0; kt < CC; kt += 16) {
        float4 va = *(const float4*)(X + (size_t)(m0 + arow) * CC + kt + ac4);
        sA[ac4 + 0][arow] = va.x;
        sA[ac4 + 1][arow] = va.y;
        sA[ac4 + 2][arow] = va.z;
        sA[ac4 + 3][arow] = va.w;
#pragma unroll
        for (int p = 0; p < 2; p++) {
            int idx = tid + p * 256;        // f4 index 0..511
            int r   = idx >> 5;             // 32 f4 per row
            int c4  = (idx & 31) * 4;
            *(float4*)&sB[r][c4] = *(const float4*)(wo + (size_t)(kt + r) * OO + c4);
        }
        __syncthreads();
#pragma unroll
        for (int k = 0; k < 16; k++) {
            float a[8], bv[4];
#pragma unroll
            for (int i = 0; i < 8; i++) a[i] = sA[k][ty + i * 8];
#pragma unroll
            for (int j = 0; j < 4; j++) bv[j] = sB[k][tx + j * 32];
#pragma unroll
            for (int i = 0; i < 8; i++)
#pragma unroll
                for (int j = 0; j < 4; j++)
                    acc[i][j] = fmaf(a[i], bv[j], acc[i][j]);
        }
        __syncthreads();
    }

    float bov[4];
#pragma unroll
    for (int j = 0; j < 4; j++) bov[j] = bo[tx + j * 32];

#pragma unroll
    for (int i = 0; i < 8; i++) {
        int mg   = m0 + ty + i * 8;
        int slot = g_pos[mg];
        if (slot >= 0) {
            float s = g_scores[mg];
            int brow = (mg & ~(NN - 1)) + slot;     // b*NN + slot
            float* out = kp_out + (size_t)brow * OO;
#pragma unroll
            for (int j = 0; j < 4; j++)
                out[tx + j * 32] = fmaf(s, acc[i][j], bov[j]);
        }
    }
}

// =====================================================================
// Kernel 4: coords scatter + point_mask + zero-fill of unselected tail
// =====================================================================
__global__ __launch_bounds__(256) void k_finalize(
    const float* __restrict__ coords, float* __restrict__ kp_out,
    float* __restrict__ co_out, float* __restrict__ mk_out)
{
    const int gid = blockIdx.x * 256 + threadIdx.x;   // over MTOT
    const int b = gid >> 14;
    const int j = gid & (NN - 1);
    const int cnt = g_counts[b];
    if (j < cnt) {
        int n = g_src[gid];
        const float* c = coords + ((size_t)(b << 14) + n) * 3;
        float c0 = c[0], c1 = c[1], c2 = c[2];
        co_out[(size_t)gid * 3 + 0] = c0;
        co_out[(size_t)gid * 3 + 1] = c1;
        co_out[(size_t)gid * 3 + 2] = c2;
        mk_out[gid] = ((c0 == 0.f) || (c1 == 0.f) || (c2 == 0.f)) ? 1.f : 0.f;
    } else {
        co_out[(size_t)gid * 3 + 0] = 0.f;
        co_out[(size_t)gid * 3 + 1] = 0.f;
        co_out[(size_t)gid * 3 + 2] = 0.f;
        mk_out[gid] = 1.f;
        float4* kp = (float4*)(kp_out + (size_t)gid * OO);
#pragma unroll
        for (int o = 0; o < OO / 4; o++)
            kp[o] = make_float4(0.f, 0.f, 0.f, 0.f);
    }
}

// =====================================================================
extern "C" void kernel_launch(void* const* d_in, const int* in_sizes, int n_in,
                              void* d_out, int out_size)
{
    const float* X  = (const float*)d_in[0];   // point_features [B,N,C]
    const float* PC = (const float*)d_in[1];   // point_coords   [B,N,3]
    const float* w1 = (const float*)d_in[2];   // [C,H]
    const float* b1 = (const float*)d_in[3];   // [H]
    const float* w2 = (const float*)d_in[4];   // [H,1]
    const float* b2 = (const float*)d_in[5];   // [1]
    const float* wo = (const float*)d_in[6];   // [C,O]
    const float* bo = (const float*)d_in[7];   // [O]

    float* out    = (float*)d_out;
    float* kp_out = out;                                   // [B,N,O]
    float* co_out = out + (size_t)MTOT * OO;               // [B,N,3]
    float* mk_out = co_out + (size_t)MTOT * 3;             // [B,N] (0/1)

    k1_score<<<MTOT / 64, 256>>>(X, w1, b1, w2, b2);
    k_scan<<<BB, 256>>>();
    k2_feats<<<MTOT / 64, 256>>>(X, wo, bo, kp_out);
    k_finalize<<<MTOT / 256, 256>>>(PC, kp_out, co_out, mk_out);
}

// round 2
// speedup vs baseline: 1.0022x; 1.0022x over previous
#include <cuda_runtime.h>
#include <cuda_bf16.h>
#include <math.h>

// Problem constants (fixed by the dataset)
#define BB   8
#define NN   16384
#define CC   640
#define HH   256
#define OO   128
#define MTOT (BB * NN)          // 131072
#define THRESH 0.4f

// -------- scratch (__device__ globals; no runtime allocation allowed) --------
__device__ float g_scores[MTOT];
__device__ int   g_pos[MTOT];    // slot within batch if selected, else -1
__device__ int   g_src[MTOT];    // src_of[b*NN + slot] = n (within batch)
__device__ int   g_counts[BB];

// =====================================================================
// Kernel 1: GEMM1 (X @ w1) fused with relu -> dot(w2) -> sigmoid score
// CTA tile: 64 rows x 256 cols (full H), KT=16, 256 threads, 8x8/thread
// =====================================================================
__global__ __launch_bounds__(256) void k1_score(
    const float* __restrict__ X, const float* __restrict__ w1,
    const float* __restrict__ b1, const float* __restrict__ w2,
    const float* __restrict__ b2)
{
    __shared__ float sA[16][65];    // [k][m], padded (65*4=260 => bank +4 per k-step)
    __shared__ float sB[16][256];   // [k][n]

    const int tid = threadIdx.x;
    const int tx = tid & 31;        // covers N: n = tx + j*32
    const int ty = tid >> 5;        // covers M: m = ty + i*8
    const int m0 = blockIdx.x * 64;

    float acc[8][8];
#pragma unroll
    for (int i = 0; i < 8; i++)
#pragma unroll
        for (int j = 0; j < 8; j++) acc[i][j] = 0.f;

    const int arow = tid >> 2;          // 0..63
    const int ac4  = (tid & 3) * 4;     // 0,4,8,12

    for (int kt = 0; kt < CC; kt += 16) {
        // A tile: 64 x 16, transposed into sA[k][m]
        float4 va = *(const float4*)(X + (size_t)(m0 + arow) * CC + kt + ac4);
        sA[ac4 + 0][arow] = va.x;
        sA[ac4 + 1][arow] = va.y;
        sA[ac4 + 2][arow] = va.z;
        sA[ac4 + 3][arow] = va.w;
        // B tile: 16 x 256 (w1 row-major [C,H] is already [k][n])
#pragma unroll
        for (int p = 0; p < 4; p++) {
            int idx = tid + p * 256;        // f4 index 0..1023
            int r   = idx >> 6;             // 64 f4 per row
            int c4  = (idx & 63) * 4;
            *(float4*)&sB[r][c4] = *(const float4*)(w1 + (size_t)(kt + r) * HH + c4);
        }
        __syncthreads();
#pragma unroll
        for (int k = 0; k < 16; k++) {
            float a[8], bv[8];
#pragma unroll
            for (int i = 0; i < 8; i++) a[i] = sA[k][ty + i * 8];
#pragma unroll
            for (int j = 0; j < 8; j++) bv[j] = sB[k][tx + j * 32];
#pragma unroll
            for (int i = 0; i < 8; i++)
#pragma unroll
                for (int j = 0; j < 8; j++)
                    acc[i][j] = fmaf(a[i], bv[j], acc[i][j]);
        }
        __syncthreads();
    }

    // Epilogue: relu(h + b1), dot with w2 across N via shfl, sigmoid
    float w2v[8], b1v[8];
#pragma unroll
    for (int j = 0; j < 8; j++) {
        int n = tx + j * 32;
        w2v[j] = w2[n];
        b1v[j] = b1[n];
    }
    const float b2v = b2[0];
#pragma unroll
    for (int i = 0; i < 8; i++) {
        float part = 0.f;
#pragma unroll
        for (int j = 0; j < 8; j++) {
            float h = acc[i][j] + b1v[j];
            h = fmaxf(h, 0.f);
            part = fmaf(h, w2v[j], part);
        }
#pragma unroll
        for (int o = 16; o > 0; o >>= 1)
            part += __shfl_xor_sync(0xFFFFFFFFu, part, o);
        if (tx == 0) {
            float logit = part + b2v;
            g_scores[m0 + ty + i * 8] = 1.f / (1.f + expf(-logit));
        }
    }
}

// =====================================================================
// Kernel 2: per-batch stream-compaction scan (1 CTA per batch)
// 256 threads x 64 contiguous elements each
// =====================================================================
__global__ __launch_bounds__(256) void k_scan()
{
    const int b    = blockIdx.x;
    const int base = b << 14;           // b * NN
    const int t    = threadIdx.x;
    const int chunk = t * 64;

    int c = 0;
    for (int e = 0; e < 64; e++)
        c += (g_scores[base + chunk + e] > THRESH) ? 1 : 0;

    // block exclusive scan of per-thread counts
    const int lane = t & 31, wid = t >> 5;
    int v = c;
#pragma unroll
    for (int o = 1; o < 32; o <<= 1) {
        int u = __shfl_up_sync(0xFFFFFFFFu, v, o);
        if (lane >= o) v += u;
    }
    __shared__ int wsum[8];
    if (lane == 31) wsum[wid] = v;
    __syncthreads();
    int woff = 0;
    for (int w = 0; w < wid; w++) woff += wsum[w];
    int p = woff + v - c;               // exclusive prefix for this thread

    for (int e = 0; e < 64; e++) {
        int n = chunk + e;
        bool sel = g_scores[base + n] > THRESH;
        if (sel) {
            g_pos[base + n] = p;
            g_src[base + p] = n;
            p++;
        } else {
            g_pos[base + n] = -1;
        }
    }
    if (t == 255) g_counts[b] = p;      // total selected in batch
}

// =====================================================================
// Kernel 3: GEMM2 (X @ wo), epilogue scales by score and scatters the
// row directly into its compacted output slot.
// CTA tile 64 x 128, KT=16, 256 threads, 8x4/thread
// =====================================================================
__global__ __launch_bounds__(256) void k2_feats(
    const float* __restrict__ X, const float* __restrict__ wo,
    const float* __restrict__ bo, float* __restrict__ kp_out)
{
    __shared__ float sA[16][65];
    __shared__ float sB[16][128];

    const int tid = threadIdx.x;
    const int tx = tid & 31;
    const int ty = tid >> 5;
    const int m0 = blockIdx.x * 64;

    float acc[8][4];
#pragma unroll
    for (int i = 0; i < 8; i++)
#pragma unroll
        for (int j = 0; j < 4; j++) acc[i][j] = 0.f;

    const int arow = tid >> 2;
    const int ac4  = (tid & 3) * 4;

    for (int kt = 0; kt < CC; kt += 16) {
        float4 va = *(const float4*)(X + (size_t)(m0 + arow) * CC + kt + ac4);
        sA[ac4 + 0][arow] = va.x;
        sA[ac4 + 1][arow] = va.y;
        sA[ac4 + 2][arow] = va.z;
        sA[ac4 + 3][arow] = va.w;
#pragma unroll
        for (int p = 0; p < 2; p++) {
            int idx = tid + p * 256;        // f4 index 0..511
            int r   = idx >> 5;             // 32 f4 per row
            int c4  = (idx & 31) * 4;
            *(float4*)&sB[r][c4] = *(const float4*)(wo + (size_t)(kt + r) * OO + c4);
        }
        __syncthreads();
#pragma unroll
        for (int k = 0; k < 16; k++) {
            float a[8], bv[4];
#pragma unroll
            for (int i = 0; i < 8; i++) a[i] = sA[k][ty + i * 8];
#pragma unroll
            for (int j = 0; j < 4; j++) bv[j] = sB[k][tx + j * 32];
#pragma unroll
            for (int i = 0; i < 8; i++)
#pragma unroll
                for (int j = 0; j < 4; j++)
                    acc[i][j] = fmaf(a[i], bv[j], acc[i][j]);
        }
        __syncthreads();
    }

    float bov[4];
#pragma unroll
    for (int j = 0; j < 4; j++) bov[j] = bo[tx + j * 32];

#pragma unroll
    for (int i = 0; i < 8; i++) {
        int mg   = m0 + ty + i * 8;
        int slot = g_pos[mg];
        if (slot >= 0) {
            float s = g_scores[mg];
            int brow = (mg & ~(NN - 1)) + slot;     // b*NN + slot
            float* out = kp_out + (size_t)brow * OO;
#pragma unroll
            for (int j = 0; j < 4; j++)
                out[tx + j * 32] = fmaf(s, acc[i][j], bov[j]);
        }
    }
}

// =====================================================================
// Kernel 4: coords scatter + point_mask + zero-fill of unselected tail
// =====================================================================
__global__ __launch_bounds__(256) void k_finalize(
    const float* __restrict__ coords, float* __restrict__ kp_out,
    float* __restrict__ co_out, float* __restrict__ mk_out)
{
    const int gid = blockIdx.x * 256 + threadIdx.x;   // over MTOT
    const int b = gid >> 14;
    const int j = gid & (NN - 1);
    const int cnt = g_counts[b];
    if (j < cnt) {
        int n = g_src[gid];
        const float* c = coords + ((size_t)(b << 14) + n) * 3;
        float c0 = c[0], c1 = c[1], c2 = c[2];
        co_out[(size_t)gid * 3 + 0] = c0;
        co_out[(size_t)gid * 3 + 1] = c1;
        co_out[(size_t)gid * 3 + 2] = c2;
        mk_out[gid] = ((c0 == 0.f) || (c1 == 0.f) || (c2 == 0.f)) ? 1.f : 0.f;
    } else {
        co_out[(size_t)gid * 3 + 0] = 0.f;
        co_out[(size_t)gid * 3 + 1] = 0.f;
        co_out[(size_t)gid * 3 + 2] = 0.f;
        mk_out[gid] = 1.f;
        float4* kp = (float4*)(kp_out + (size_t)gid * OO);
#pragma unroll
        for (int o = 0; o < OO / 4; o++)
            kp[o] = make_float4(0.f, 0.f, 0.f, 0.f);
    }
}

// =====================================================================
extern "C" void kernel_launch(void* const* d_in, const int* in_sizes, int n_in,
                              void* d_out, int out_size)
{
    const float* X  = (const float*)d_in[0];   // point_features [B,N,C]
    const float* PC = (const float*)d_in[1];   // point_coords   [B,N,3]
    const float* w1 = (const float*)d_in[2];   // [C,H]
    const float* b1 = (const float*)d_in[3];   // [H]
    const float* w2 = (const float*)d_in[4];   // [H,1]
    const float* b2 = (const float*)d_in[5];   // [1]
    const float* wo = (const float*)d_in[6];   // [C,O]
    const float* bo = (const float*)d_in[7];   // [O]

    float* out    = (float*)d_out;
    float* kp_out = out;                                   // [B,N,O]
    float* co_out = out + (size_t)MTOT * OO;               // [B,N,3]
    float* mk_out = co_out + (size_t)MTOT * 3;             // [B,N] (0/1)

    k1_score<<<MTOT / 64, 256>>>(X, w1, b1, w2, b2);
    k_scan<<<BB, 256>>>();
    k2_feats<<<MTOT / 64, 256>>>(X, wo, bo, kp_out);
    k_finalize<<<MTOT / 256, 256>>>(PC, kp_out, co_out, mk_out);
}

// round 4
// speedup vs baseline: 2.1204x; 2.1157x over previous
#include <cuda_runtime.h>
#include <cuda_bf16.h>
#include <math.h>
#include <stdint.h>

// ---------------- problem constants ----------------
#define BB   8
#define NN   16384
#define CC   640
#define HH   256
#define OO   128
#define MTOT (BB * NN)          // 131072
#define THRESH 0.4f

// ---------------- tiling ----------------
#define MT      64              // M rows per CTA
#define NB      (HH + OO)       // 384 stacked B rows (w1 then wo)
#define NCH     (CC / 16)       // 40 k-chunks of 16
#define RSTRIDE 48              // smem row stride bytes (16 bf16 = 32B data, padded)

// per-stage smem: A_hi | A_lo | B_hi | B_lo
#define ST_A_HI   0
#define ST_A_LO   (MT * RSTRIDE)                 // 3072
#define ST_B_HI   (2 * MT * RSTRIDE)             // 6144
#define ST_B_LO   (ST_B_HI + NB * RSTRIDE)       // 24576
#define STAGE_SZ  (ST_B_LO + NB * RSTRIDE)       // 43008
#define NSTAGE    3
#define SM_HDR    1024                            // part[128] + sscore[64]
#define SMEM_TOTAL (SM_HDR + NSTAGE * STAGE_SZ)   // 130048

// weight image: [chunk][half(hi/lo)][row 0..383][16 bf16]  (24576 B per chunk)
#define WCHUNK_B  (2 * NB * 16 * 2)               // 24576 bytes

// ---------------- scratch ----------------
__device__ float g_scores[MTOT];
__device__ int   g_src[MTOT];
__device__ int   g_counts[BB];
__device__ float g_feats[(size_t)MTOT * OO];              // 64 MB
__device__ __nv_bfloat16 g_w[NCH * 2 * NB * 16];          // 1.92 MB

// ---------------- helpers ----------------
__device__ __forceinline__ uint32_t smem_u32(const void* p) {
    uint32_t a;
    asm("{ .reg .u64 t; cvta.to.shared.u64 t, %1; cvt.u32.u64 %0, t; }" : "=r"(a) : "l"(p));
    return a;
}

__device__ __forceinline__ void ldsm_x4(uint32_t& r0, uint32_t& r1, uint32_t& r2, uint32_t& r3, uint32_t a) {
    asm volatile("ldmatrix.sync.aligned.m8n8.x4.shared.b16 {%0,%1,%2,%3}, [%4];"
                 : "=r"(r0), "=r"(r1), "=r"(r2), "=r"(r3) : "r"(a));
}
__device__ __forceinline__ void ldsm_x2(uint32_t& r0, uint32_t& r1, uint32_t a) {
    asm volatile("ldmatrix.sync.aligned.m8n8.x2.shared.b16 {%0,%1}, [%2];"
                 : "=r"(r0), "=r"(r1) : "r"(a));
}
__device__ __forceinline__ void mma16816(float* c, uint32_t a0, uint32_t a1, uint32_t a2, uint32_t a3,
                                         uint32_t b0, uint32_t b1) {
    asm volatile(
        "mma.sync.aligned.m16n8k16.row.col.f32.bf16.bf16.f32 "
        "{%0,%1,%2,%3}, {%4,%5,%6,%7}, {%8,%9}, {%0,%1,%2,%3};"
        : "+f"(c[0]), "+f"(c[1]), "+f"(c[2]), "+f"(c[3])
        : "r"(a0), "r"(a1), "r"(a2), "r"(a3), "r"(b0), "r"(b1));
}
__device__ __forceinline__ void cp16(uint32_t dst, const void* src) {
    asm volatile("cp.async.cg.shared.global [%0], [%1], 16;" :: "r"(dst), "l"(src));
}
#define CP_COMMIT() asm volatile("cp.async.commit_group;" ::: "memory")
#define CP_WAIT(n)  asm volatile("cp.async.wait_group %0;" :: "n"(n) : "memory")

__device__ __forceinline__ uint32_t pack_bf2(float x, float y) {
    __nv_bfloat16 hx = __float2bfloat16(x), hy = __float2bfloat16(y);
    return (uint32_t)__bfloat16_as_ushort(hx) | ((uint32_t)__bfloat16_as_ushort(hy) << 16);
}

// =====================================================================
// Prologue: weights fp32 -> (hi, lo) bf16 packed image
// =====================================================================
__global__ __launch_bounds__(256) void k_wconv(const float* __restrict__ w1,
                                               const float* __restrict__ wo)
{
    int g = blockIdx.x * 256 + threadIdx.x;       // over NCH*NB*16 = 245760
    if (g >= NCH * NB * 16) return;
    int c   = g / (NB * 16);
    int rem = g - c * (NB * 16);
    int r   = rem >> 4;
    int kk  = rem & 15;
    int k   = c * 16 + kk;
    float v = (r < HH) ? w1[(size_t)k * HH + r] : wo[(size_t)k * OO + (r - HH)];
    __nv_bfloat16 h = __float2bfloat16(v);
    __nv_bfloat16 l = __float2bfloat16(v - __bfloat162float(h));
    g_w[((size_t)(c * 2 + 0) * NB + r) * 16 + kk] = h;
    g_w[((size_t)(c * 2 + 1) * NB + r) * 16 + kk] = l;
}

// =====================================================================
// Main fused kernel (mma.sync bf16 split, 3 products)
// =====================================================================
__device__ __forceinline__ void copyB_async(uint32_t sb, int st, int ch, int tid) {
    const char* src = (const char*)g_w + (size_t)ch * WCHUNK_B;
    uint32_t dstb = sb + SM_HDR + st * STAGE_SZ + ST_B_HI;
#pragma unroll
    for (int i = 0; i < 6; i++) {
        int p = tid + i * 256;                 // 16B unit index 0..1535
        int half = p / 768;                    // 0 = hi, 1 = lo
        int pr = p - half * 768;
        int row = pr >> 1;
        int h = pr & 1;
        uint32_t dst = dstb + half * (NB * RSTRIDE) + row * RSTRIDE + h * 16;
        cp16(dst, src + (size_t)p * 16);
    }
}

__device__ __forceinline__ void convA_st(uint32_t sb, int st, float4 v, int arow, int aq) {
    uint32_t h0 = pack_bf2(v.x, v.y);
    uint32_t h1 = pack_bf2(v.z, v.w);
    float rx = v.x - __bfloat162float(__float2bfloat16(v.x));
    float ry = v.y - __bfloat162float(__float2bfloat16(v.y));
    float rz = v.z - __bfloat162float(__float2bfloat16(v.z));
    float rw = v.w - __bfloat162float(__float2bfloat16(v.w));
    uint32_t l0 = pack_bf2(rx, ry);
    uint32_t l1 = pack_bf2(rz, rw);
    uint32_t base = sb + SM_HDR + st * STAGE_SZ + arow * RSTRIDE + aq * 8;
    asm volatile("st.shared.v2.b32 [%0], {%1,%2};" :: "r"(base + ST_A_HI), "r"(h0), "r"(h1) : "memory");
    asm volatile("st.shared.v2.b32 [%0], {%1,%2};" :: "r"(base + ST_A_LO), "r"(l0), "r"(l1) : "memory");
}

__global__ __launch_bounds__(256, 1) void k_main(
    const float* __restrict__ X,
    const float* __restrict__ b1, const float* __restrict__ w2,
    const float* __restrict__ b2, const float* __restrict__ bo)
{
    extern __shared__ char smem[];
    const uint32_t sb = smem_u32(smem);
    const int tid = threadIdx.x;
    const int wid = tid >> 5;
    const int lane = tid & 31;
    const int mw = wid & 3;            // M warp (16 rows each)
    const int nw = wid >> 2;           // N warp (192 cols each)
    const int q = lane & 3;
    const int r = lane >> 2;
    const int m0 = blockIdx.x * MT;

    float* part   = (float*)smem;          // [2][64]
    float* sscore = (float*)smem + 128;    // [64]

    // A prefetch mapping: thread -> (row = tid/4, quad = tid%4 -> 4 floats)
    const int arow = tid >> 2;
    const int aq = tid & 3;
    const float* aptr = X + (size_t)(m0 + arow) * CC + aq * 4;

    // ---- prologue ----
    float4 areg = *(const float4*)(aptr);               // chunk 0
    copyB_async(sb, 0, 0, tid); CP_COMMIT();
    convA_st(sb, 0, areg, arow, aq);
    areg = *(const float4*)(aptr + 16);                 // chunk 1
    copyB_async(sb, 1, 1, tid); CP_COMMIT();
    CP_WAIT(1);                                          // B0 done
    __syncthreads();

    float c[96];
#pragma unroll
    for (int i = 0; i < 96; i++) c[i] = 0.f;

    // ldmatrix lane-relative offsets
    const uint32_t aoff = (mw * 16 + (lane & 15)) * RSTRIDE + ((lane >> 4) << 4);
    const uint32_t boff = (lane & 7) * RSTRIDE + (((lane >> 3) & 1) << 4);
    const int n0 = nw * 192;

    for (int ch = 0; ch < NCH; ch++) {
        const uint32_t stb = sb + SM_HDR + (ch % NSTAGE) * STAGE_SZ;
        uint32_t ah0, ah1, ah2, ah3, al0, al1, al2, al3;
        ldsm_x4(ah0, ah1, ah2, ah3, stb + ST_A_HI + aoff);
        ldsm_x4(al0, al1, al2, al3, stb + ST_A_LO + aoff);
        const uint32_t bh_base = stb + ST_B_HI + n0 * RSTRIDE + boff;
#pragma unroll
        for (int j = 0; j < 24; j++) {
            uint32_t bh0, bh1, bl0, bl1;
            ldsm_x2(bh0, bh1, bh_base + j * 8 * RSTRIDE);
            ldsm_x2(bl0, bl1, bh_base + (NB * RSTRIDE) + j * 8 * RSTRIDE);
            float* cj = c + j * 4;
            mma16816(cj, ah0, ah1, ah2, ah3, bh0, bh1);   // hi*hi
            mma16816(cj, al0, al1, al2, al3, bh0, bh1);   // lo*hi
            mma16816(cj, ah0, ah1, ah2, ah3, bl0, bl1);   // hi*lo
        }

        if (ch + 1 < NCH) {
            convA_st(sb, (ch + 1) % NSTAGE, areg, arow, aq);
            if (ch + 2 < NCH) {
                areg = *(const float4*)(aptr + (size_t)(ch + 2) * 16);
                copyB_async(sb, (ch + 2) % NSTAGE, ch + 2, tid); CP_COMMIT();
                CP_WAIT(1);                 // B(ch+1) done
            } else {
                CP_WAIT(0);                 // last group done
            }
            __syncthreads();
        }
    }

    // ---- score partials: relu(h+b1)·w2 over this warp's columns < 256 ----
    {
        float pr = 0.f, pr8 = 0.f;
        const int jmax = (nw == 0) ? 24 : 8;
#pragma unroll
        for (int j = 0; j < 24; j++) {
            if (j >= jmax) break;
            int col = n0 + j * 8 + 2 * q;
            float w2a = w2[col], w2b = w2[col + 1];
            float b1a = b1[col], b1b = b1[col + 1];
            const float* cj = c + j * 4;
            pr  = fmaf(fmaxf(cj[0] + b1a, 0.f), w2a, pr);
            pr  = fmaf(fmaxf(cj[1] + b1b, 0.f), w2b, pr);
            pr8 = fmaf(fmaxf(cj[2] + b1a, 0.f), w2a, pr8);
            pr8 = fmaf(fmaxf(cj[3] + b1b, 0.f), w2b, pr8);
        }
        pr  += __shfl_xor_sync(0xFFFFFFFFu, pr, 1);
        pr  += __shfl_xor_sync(0xFFFFFFFFu, pr, 2);
        pr8 += __shfl_xor_sync(0xFFFFFFFFu, pr8, 1);
        pr8 += __shfl_xor_sync(0xFFFFFFFFu, pr8, 2);
        if (q == 0) {
            part[nw * 64 + mw * 16 + r]     = pr;
            part[nw * 64 + mw * 16 + r + 8] = pr8;
        }
    }
    __syncthreads();

    if (tid < 64) {
        float logit = part[tid] + part[64 + tid] + b2[0];
        float s = 1.f / (1.f + expf(-logit));
        g_scores[m0 + tid] = s;
        sscore[tid] = s;
    }
    __syncthreads();

    // ---- feats: cols 256..383 (nw==1, j 8..23), scaled by score + bo ----
    if (nw == 1) {
#pragma unroll
        for (int j = 8; j < 24; j++) {
            int fcol = (j - 8) * 8 + 2 * q;
            int row = mw * 16 + r;
            float s1 = sscore[row], s2 = sscore[row + 8];
            float boa = bo[fcol], bob = bo[fcol + 1];
            const float* cj = c + j * 4;
            float2 v1 = make_float2(fmaf(s1, cj[0], boa), fmaf(s1, cj[1], bob));
            float2 v2 = make_float2(fmaf(s2, cj[2], boa), fmaf(s2, cj[3], bob));
            *(float2*)(g_feats + (size_t)(m0 + row) * OO + fcol) = v1;
            *(float2*)(g_feats + (size_t)(m0 + row + 8) * OO + fcol) = v2;
        }
    }
}

// =====================================================================
// Per-batch stream-compaction scan (1 CTA per batch)
// =====================================================================
__global__ __launch_bounds__(256) void k_scan()
{
    const int b = blockIdx.x;
    const int base = b << 14;
    const int t = threadIdx.x;
    const int chunk = t * 64;

    int c = 0;
    for (int e = 0; e < 64; e++)
        c += (g_scores[base + chunk + e] > THRESH) ? 1 : 0;

    const int lane = t & 31, wid = t >> 5;
    int v = c;
#pragma unroll
    for (int o = 1; o < 32; o <<= 1) {
        int u = __shfl_up_sync(0xFFFFFFFFu, v, o);
        if (lane >= o) v += u;
    }
    __shared__ int wsum[8];
    if (lane == 31) wsum[wid] = v;
    __syncthreads();
    int woff = 0;
    for (int w = 0; w < wid; w++) woff += wsum[w];
    int p = woff + v - c;

    for (int e = 0; e < 64; e++) {
        int n = chunk + e;
        if (g_scores[base + n] > THRESH) {
            g_src[base + p] = n;
            p++;
        }
    }
    if (t == 255) g_counts[b] = p;
}

// =====================================================================
// Finalize: warp-per-row gather g_feats[src] -> kp_out[slot], coords, mask
// =====================================================================
__global__ __launch_bounds__(256) void k_final(
    const float* __restrict__ coords, float* __restrict__ kp,
    float* __restrict__ co, float* __restrict__ mk)
{
    const int w = blockIdx.x * 8 + (threadIdx.x >> 5);
    const int lane = threadIdx.x & 31;
    const int b = w >> 14;
    const int j = w & (NN - 1);
    const int cnt = g_counts[b];
    float4* dst = (float4*)(kp + (size_t)w * OO);
    if (j < cnt) {
        const int srow = (b << 14) + g_src[w];
        const float4* src = (const float4*)(g_feats + (size_t)srow * OO);
        dst[lane] = src[lane];
        if (lane == 0) {
            float c0 = coords[(size_t)srow * 3 + 0];
            float c1 = coords[(size_t)srow * 3 + 1];
            float c2 = coords[(size_t)srow * 3 + 2];
            co[(size_t)w * 3 + 0] = c0;
            co[(size_t)w * 3 + 1] = c1;
            co[(size_t)w * 3 + 2] = c2;
            mk[w] = ((c0 == 0.f) || (c1 == 0.f) || (c2 == 0.f)) ? 1.f : 0.f;
        }
    } else {
        dst[lane] = make_float4(0.f, 0.f, 0.f, 0.f);
        if (lane == 0) {
            co[(size_t)w * 3 + 0] = 0.f;
            co[(size_t)w * 3 + 1] = 0.f;
            co[(size_t)w * 3 + 2] = 0.f;
            mk[w] = 1.f;
        }
    }
}

// =====================================================================
extern "C" void kernel_launch(void* const* d_in, const int* in_sizes, int n_in,
                              void* d_out, int out_size)
{
    const float* X  = (const float*)d_in[0];
    const float* PC = (const float*)d_in[1];
    const float* w1 = (const float*)d_in[2];
    const float* b1 = (const float*)d_in[3];
    const float* w2 = (const float*)d_in[4];
    const float* b2 = (const float*)d_in[5];
    const float* wo = (const float*)d_in[6];
    const float* bo = (const float*)d_in[7];

    float* out    = (float*)d_out;
    float* kp_out = out;                                   // [B,N,O]
    float* co_out = out + (size_t)MTOT * OO;               // [B,N,3]
    float* mk_out = co_out + (size_t)MTOT * 3;             // [B,N]

    static int smem_set = 0;
    if (!smem_set) {
        cudaFuncSetAttribute(k_main, cudaFuncAttributeMaxDynamicSharedMemorySize, SMEM_TOTAL);
        smem_set = 1;
    }

    k_wconv<<<(NCH * NB * 16 + 255) / 256, 256>>>(w1, wo);
    k_main<<<MTOT / MT, 256, SMEM_TOTAL>>>(X, b1, w2, b2, bo);
    k_scan<<<BB, 256>>>();
    k_final<<<MTOT / 8, 256>>>(PC, kp_out, co_out, mk_out);
}

// round 5
// speedup vs baseline: 2.4043x; 1.1339x over previous
#include <cuda_runtime.h>
#include <cuda_bf16.h>
#include <math.h>
#include <stdint.h>

// ---------------- problem constants ----------------
#define BB   8
#define NN   16384
#define CC   640
#define HH   256
#define OO   128
#define MTOT (BB * NN)          // 131072
#define THRESH 0.4f

// ---------------- tiling ----------------
#define MT      64              // M rows per CTA
#define NB      (HH + OO)       // 384 stacked B rows (w1 then wo)
#define NCH     (CC / 16)       // 40 k-chunks of 16
#define RSTRIDE 48              // smem row stride bytes (16 bf16 = 32B data, padded)
#define NTHR    512             // 16 warps: P=2 (M) x Q=8 (N)

// per-stage smem: A_hi | A_lo | B_hi | B_lo
#define ST_A_HI   0
#define ST_A_LO   (MT * RSTRIDE)                 // 3072
#define ST_B_HI   (2 * MT * RSTRIDE)             // 6144
#define ST_B_LO   (ST_B_HI + NB * RSTRIDE)       // 24576
#define STAGE_SZ  (ST_B_LO + NB * RSTRIDE)       // 43008
#define NSTAGE    3
#define SM_HDR    2048                            // part[6][64] + sscore[64]
#define SMEM_TOTAL (SM_HDR + NSTAGE * STAGE_SZ)   // 131072

// weight image: [chunk][half(hi/lo)][row 0..383][16 bf16]  (24576 B per chunk)
#define WCHUNK_B  (2 * NB * 16 * 2)

// ---------------- scratch ----------------
__device__ float g_scores[MTOT];
__device__ int   g_src[MTOT];
__device__ int   g_counts[BB];
__device__ float g_feats[(size_t)MTOT * OO];              // 64 MB
__device__ __nv_bfloat16 g_w[NCH * 2 * NB * 16];          // 1.92 MB

// ---------------- helpers ----------------
__device__ __forceinline__ uint32_t smem_u32(const void* p) {
    uint32_t a;
    asm("{ .reg .u64 t; cvta.to.shared.u64 t, %1; cvt.u32.u64 %0, t; }" : "=r"(a) : "l"(p));
    return a;
}
__device__ __forceinline__ void ldsm_x4(uint32_t& r0, uint32_t& r1, uint32_t& r2, uint32_t& r3, uint32_t a) {
    asm volatile("ldmatrix.sync.aligned.m8n8.x4.shared.b16 {%0,%1,%2,%3}, [%4];"
                 : "=r"(r0), "=r"(r1), "=r"(r2), "=r"(r3) : "r"(a));
}
__device__ __forceinline__ void mma16816(float* c, uint32_t a0, uint32_t a1, uint32_t a2, uint32_t a3,
                                         uint32_t b0, uint32_t b1) {
    asm volatile(
        "mma.sync.aligned.m16n8k16.row.col.f32.bf16.bf16.f32 "
        "{%0,%1,%2,%3}, {%4,%5,%6,%7}, {%8,%9}, {%0,%1,%2,%3};"
        : "+f"(c[0]), "+f"(c[1]), "+f"(c[2]), "+f"(c[3])
        : "r"(a0), "r"(a1), "r"(a2), "r"(a3), "r"(b0), "r"(b1));
}
__device__ __forceinline__ void cp16(uint32_t dst, const void* src) {
    asm volatile("cp.async.cg.shared.global [%0], [%1], 16;" :: "r"(dst), "l"(src));
}
#define CP_COMMIT() asm volatile("cp.async.commit_group;" ::: "memory")
#define CP_WAIT(n)  asm volatile("cp.async.wait_group %0;" :: "n"(n) : "memory")

__device__ __forceinline__ uint32_t pack_bf2(float x, float y) {
    __nv_bfloat16 hx = __float2bfloat16(x), hy = __float2bfloat16(y);
    return (uint32_t)__bfloat16_as_ushort(hx) | ((uint32_t)__bfloat16_as_ushort(hy) << 16);
}

// =====================================================================
// Prologue: weights fp32 -> (hi, lo) bf16 packed image
// =====================================================================
__global__ __launch_bounds__(256) void k_wconv(const float* __restrict__ w1,
                                               const float* __restrict__ wo)
{
    int g = blockIdx.x * 256 + threadIdx.x;
    if (g >= NCH * NB * 16) return;
    int c   = g / (NB * 16);
    int rem = g - c * (NB * 16);
    int r   = rem >> 4;
    int kk  = rem & 15;
    int k   = c * 16 + kk;
    float v = (r < HH) ? w1[(size_t)k * HH + r] : wo[(size_t)k * OO + (r - HH)];
    __nv_bfloat16 h = __float2bfloat16(v);
    __nv_bfloat16 l = __float2bfloat16(v - __bfloat162float(h));
    g_w[((size_t)(c * 2 + 0) * NB + r) * 16 + kk] = h;
    g_w[((size_t)(c * 2 + 1) * NB + r) * 16 + kk] = l;
}

// =====================================================================
// Main fused kernel
// =====================================================================
__device__ __forceinline__ void copyB_async(uint32_t sb, int st, int ch, int tid) {
    const char* src = (const char*)g_w + (size_t)ch * WCHUNK_B;
    uint32_t dstb = sb + SM_HDR + st * STAGE_SZ + ST_B_HI;
#pragma unroll
    for (int i = 0; i < 3; i++) {
        int p = tid + i * NTHR;                // 16B unit index 0..1535
        int half = p / 768;                    // 0 = hi, 1 = lo
        int pr = p - half * 768;
        int row = pr >> 1;
        int h = pr & 1;
        uint32_t dst = dstb + half * (NB * RSTRIDE) + row * RSTRIDE + h * 16;
        cp16(dst, src + (size_t)p * 16);
    }
}

// thread t: row = t>>3 (0..63), pr = t&7 (float2 index); stores 2 bf16 hi + 2 lo
__device__ __forceinline__ void convA_st(uint32_t sb, int st, float2 v, int arow, int apr) {
    uint32_t h0 = pack_bf2(v.x, v.y);
    float rx = v.x - __bfloat162float(__float2bfloat16(v.x));
    float ry = v.y - __bfloat162float(__float2bfloat16(v.y));
    uint32_t l0 = pack_bf2(rx, ry);
    uint32_t base = sb + SM_HDR + st * STAGE_SZ + arow * RSTRIDE + apr * 4;
    asm volatile("st.shared.b32 [%0], %1;" :: "r"(base + ST_A_HI), "r"(h0) : "memory");
    asm volatile("st.shared.b32 [%0], %1;" :: "r"(base + ST_A_LO), "r"(l0) : "memory");
}

__global__ __launch_bounds__(NTHR, 1) void k_main(
    const float* __restrict__ X,
    const float* __restrict__ b1, const float* __restrict__ w2,
    const float* __restrict__ b2, const float* __restrict__ bo)
{
    extern __shared__ char smem[];
    const uint32_t sb = smem_u32(smem);
    const int tid = threadIdx.x;
    const int wid = tid >> 5;
    const int lane = tid & 31;
    const int nw = wid & 7;            // N warp group: 48 cols each
    const int mw = wid >> 3;           // M warp group: 32 rows each
    const int q = lane & 3;
    const int r = lane >> 2;
    const int m0 = blockIdx.x * MT;
    const int n0 = nw * 48;

    float* part   = (float*)smem;          // [6][64]
    float* sscore = (float*)smem + 384;    // [64]

    // A prefetch mapping: thread -> (row = tid>>3, float2 pair = tid&7)
    const int arow = tid >> 3;
    const int apr = tid & 7;
    const float* aptr = X + (size_t)(m0 + arow) * CC + apr * 2;

    // ---- prologue ----
    float2 areg = *(const float2*)(aptr);               // chunk 0
    copyB_async(sb, 0, 0, tid); CP_COMMIT();
    convA_st(sb, 0, areg, arow, apr);
    areg = *(const float2*)(aptr + 16);                 // chunk 1
    copyB_async(sb, 1, 1, tid); CP_COMMIT();
    CP_WAIT(1);                                          // B0 done
    __syncthreads();

    float c[48];
#pragma unroll
    for (int i = 0; i < 48; i++) c[i] = 0.f;

    // ldmatrix lane offsets
    // A (m16xk16 x4): lanes 0-15 rows, lanes 16-31 k-upper 16B
    const uint32_t aoff0 = (uint32_t)((mw * 32 + (lane & 15)) * RSTRIDE + ((lane >> 4) << 4));
    const uint32_t aoff1 = aoff0 + 16 * RSTRIDE;
    // B (n16xk16 x4): groups of 8 lanes -> (n0-7 klo, n0-7 khi, n8-15 klo, n8-15 khi)
    const uint32_t boff = (uint32_t)(((lane & 7) + ((lane >> 4) << 3)) * RSTRIDE + (((lane >> 3) & 1) << 4));

    for (int ch = 0; ch < NCH; ch++) {
        const uint32_t stb = sb + SM_HDR + (ch % NSTAGE) * STAGE_SZ;
        uint32_t ah[2][4], al[2][4];
        ldsm_x4(ah[0][0], ah[0][1], ah[0][2], ah[0][3], stb + ST_A_HI + aoff0);
        ldsm_x4(ah[1][0], ah[1][1], ah[1][2], ah[1][3], stb + ST_A_HI + aoff1);
        ldsm_x4(al[0][0], al[0][1], al[0][2], al[0][3], stb + ST_A_LO + aoff0);
        ldsm_x4(al[1][0], al[1][1], al[1][2], al[1][3], stb + ST_A_LO + aoff1);
        const uint32_t bb = stb + ST_B_HI + (uint32_t)(n0 * RSTRIDE) + boff;
#pragma unroll
        for (int jp = 0; jp < 3; jp++) {
            uint32_t bh[4], bl[4];
            ldsm_x4(bh[0], bh[1], bh[2], bh[3], bb + jp * 16 * RSTRIDE);
            ldsm_x4(bl[0], bl[1], bl[2], bl[3], bb + (NB * RSTRIDE) + jp * 16 * RSTRIDE);
#pragma unroll
            for (int t = 0; t < 2; t++) {
#pragma unroll
                for (int s = 0; s < 2; s++) {
                    float* cj = c + (t * 6 + jp * 2 + s) * 4;
                    mma16816(cj, ah[t][0], ah[t][1], ah[t][2], ah[t][3], bh[2*s], bh[2*s+1]); // hi*hi
                    mma16816(cj, al[t][0], al[t][1], al[t][2], al[t][3], bh[2*s], bh[2*s+1]); // lo*hi
                    mma16816(cj, ah[t][0], ah[t][1], ah[t][2], ah[t][3], bl[2*s], bl[2*s+1]); // hi*lo
                }
            }
        }

        if (ch + 1 < NCH) {
            convA_st(sb, (ch + 1) % NSTAGE, areg, arow, apr);
            if (ch + 2 < NCH) {
                areg = *(const float2*)(aptr + (size_t)(ch + 2) * 16);
                copyB_async(sb, (ch + 2) % NSTAGE, ch + 2, tid); CP_COMMIT();
                CP_WAIT(1);                 // B(ch+1) done
            } else {
                CP_WAIT(0);
            }
            __syncthreads();
        }
    }

    // ---- deterministic score reduction ----
    __syncthreads();
    if (tid < 64) {
#pragma unroll
        for (int kk = 0; kk < 6; kk++) part[kk * 64 + tid] = 0.f;
    }
    __syncthreads();

    if (nw < 6) {
        const int jmax = (nw == 5) ? 2 : 6;
#pragma unroll
        for (int t = 0; t < 2; t++) {
            float pr = 0.f, pr8 = 0.f;
#pragma unroll
            for (int j = 0; j < 6; j++) {
                if (j >= jmax) break;
                int col = n0 + j * 8 + 2 * q;
                float w2a = w2[col], w2b = w2[col + 1];
                float b1a = b1[col], b1b = b1[col + 1];
                const float* cj = c + (t * 6 + j) * 4;
                pr  = fmaf(fmaxf(cj[0] + b1a, 0.f), w2a, pr);
                pr  = fmaf(fmaxf(cj[1] + b1b, 0.f), w2b, pr);
                pr8 = fmaf(fmaxf(cj[2] + b1a, 0.f), w2a, pr8);
                pr8 = fmaf(fmaxf(cj[3] + b1b, 0.f), w2b, pr8);
            }
            pr  += __shfl_xor_sync(0xFFFFFFFFu, pr, 1);
            pr  += __shfl_xor_sync(0xFFFFFFFFu, pr, 2);
            pr8 += __shfl_xor_sync(0xFFFFFFFFu, pr8, 1);
            pr8 += __shfl_xor_sync(0xFFFFFFFFu, pr8, 2);
            if (q == 0) {
                int row = mw * 32 + t * 16 + r;
                part[nw * 64 + row]     = pr;
                part[nw * 64 + row + 8] = pr8;
            }
        }
    }
    __syncthreads();

    if (tid < 64) {
        float logit = b2[0];
#pragma unroll
        for (int kk = 0; kk < 6; kk++) logit += part[kk * 64 + tid];
        float s = 1.f / (1.f + expf(-logit));
        g_scores[m0 + tid] = s;
        sscore[tid] = s;
    }
    __syncthreads();

    // ---- feats: cols 256..383 live in nw 5 (j>=2), 6, 7 ----
    if (nw >= 5) {
        const int jstart = (nw == 5) ? 2 : 0;
#pragma unroll
        for (int t = 0; t < 2; t++) {
#pragma unroll
            for (int j = 0; j < 6; j++) {
                if (j < jstart) continue;
                int fcol = n0 + j * 8 - 256 + 2 * q;
                int row = mw * 32 + t * 16 + r;
                float s1 = sscore[row], s2 = sscore[row + 8];
                float boa = bo[fcol], bob = bo[fcol + 1];
                const float* cj = c + (t * 6 + j) * 4;
                float2 v1 = make_float2(fmaf(s1, cj[0], boa), fmaf(s1, cj[1], bob));
                float2 v2 = make_float2(fmaf(s2, cj[2], boa), fmaf(s2, cj[3], bob));
                *(float2*)(g_feats + (size_t)(m0 + row) * OO + fcol) = v1;
                *(float2*)(g_feats + (size_t)(m0 + row + 8) * OO + fcol) = v2;
            }
        }
    }
}

// =====================================================================
// Per-batch stream-compaction scan (1 CTA per batch)
// =====================================================================
__global__ __launch_bounds__(256) void k_scan()
{
    const int b = blockIdx.x;
    const int base = b << 14;
    const int t = threadIdx.x;
    const int chunk = t * 64;

    int c = 0;
    for (int e = 0; e < 64; e++)
        c += (g_scores[base + chunk + e] > THRESH) ? 1 : 0;

    const int lane = t & 31, wid = t >> 5;
    int v = c;
#pragma unroll
    for (int o = 1; o < 32; o <<= 1) {
        int u = __shfl_up_sync(0xFFFFFFFFu, v, o);
        if (lane >= o) v += u;
    }
    __shared__ int wsum[8];
    if (lane == 31) wsum[wid] = v;
    __syncthreads();
    int woff = 0;
    for (int w = 0; w < wid; w++) woff += wsum[w];
    int p = woff + v - c;

    for (int e = 0; e < 64; e++) {
        int n = chunk + e;
        if (g_scores[base + n] > THRESH) {
            g_src[base + p] = n;
            p++;
        }
    }
    if (t == 255) g_counts[b] = p;
}

// =====================================================================
// Finalize: warp-per-row gather g_feats[src] -> kp_out[slot], coords, mask
// =====================================================================
__global__ __launch_bounds__(256) void k_final(
    const float* __restrict__ coords, float* __restrict__ kp,
    float* __restrict__ co, float* __restrict__ mk)
{
    const int w = blockIdx.x * 8 + (threadIdx.x >> 5);
    const int lane = threadIdx.x & 31;
    const int b = w >> 14;
    const int j = w & (NN - 1);
    const int cnt = g_counts[b];
    float4* dst = (float4*)(kp + (size_t)w * OO);
    if (j < cnt) {
        const int srow = (b << 14) + g_src[w];
        const float4* src = (const float4*)(g_feats + (size_t)srow * OO);
        dst[lane] = src[lane];
        if (lane == 0) {
            float c0 = coords[(size_t)srow * 3 + 0];
            float c1 = coords[(size_t)srow * 3 + 1];
            float c2 = coords[(size_t)srow * 3 + 2];
            co[(size_t)w * 3 + 0] = c0;
            co[(size_t)w * 3 + 1] = c1;
            co[(size_t)w * 3 + 2] = c2;
            mk[w] = ((c0 == 0.f) || (c1 == 0.f) || (c2 == 0.f)) ? 1.f : 0.f;
        }
    } else {
        dst[lane] = make_float4(0.f, 0.f, 0.f, 0.f);
        if (lane == 0) {
            co[(size_t)w * 3 + 0] = 0.f;
            co[(size_t)w * 3 + 1] = 0.f;
            co[(size_t)w * 3 + 2] = 0.f;
            mk[w] = 1.f;
        }
    }
}

// =====================================================================
extern "C" void kernel_launch(void* const* d_in, const int* in_sizes, int n_in,
                              void* d_out, int out_size)
{
    const float* X  = (const float*)d_in[0];
    const float* PC = (const float*)d_in[1];
    const float* w1 = (const float*)d_in[2];
    const float* b1 = (const float*)d_in[3];
    const float* w2 = (const float*)d_in[4];
    const float* b2 = (const float*)d_in[5];
    const float* wo = (const float*)d_in[6];
    const float* bo = (const float*)d_in[7];

    float* out    = (float*)d_out;
    float* kp_out = out;                                   // [B,N,O]
    float* co_out = out + (size_t)MTOT * OO;               // [B,N,3]
    float* mk_out = co_out + (size_t)MTOT * 3;             // [B,N]

    static int smem_set = 0;
    if (!smem_set) {
        cudaFuncSetAttribute(k_main, cudaFuncAttributeMaxDynamicSharedMemorySize, SMEM_TOTAL);
        smem_set = 1;
    }

    k_wconv<<<(NCH * NB * 16 + 255) / 256, 256>>>(w1, wo);
    k_main<<<MTOT / MT, NTHR, SMEM_TOTAL>>>(X, b1, w2, b2, bo);
    k_scan<<<BB, 256>>>();
    k_final<<<MTOT / 8, 256>>>(PC, kp_out, co_out, mk_out);
}